// round 14
// baseline (speedup 1.0000x reference)
#include <cuda_runtime.h>
#include <math.h>
#include <float.h>

// RepulsionLoss: B=8, N=4096, KNN=4, H=0.03
// Single persistent kernel: prep -> scan -> scatter -> search, separated by
// grid-wide spin barriers (all 256 blocks co-resident at 2 blocks/SM).
// 2D grid pruning (64x64 cells, width 0.15): neighbors outside the 3x3 cell
// window have weight <= e^-25, negligible. Selection = exact min/max network
// over the 5 smallest (order-invariant), losses scattered to original point
// indices and reduced in fixed order -> deterministic. Self = strict min ->
// slot 0, dropped (matches reference top_k(KNN+1)-drop-first).
// R13 deadlock fix: the 8-value second-level scan now runs with ALL 32 lanes
// of warp 0 participating (no partial-mask warp collectives anywhere).

#define B_SZ     8
#define N_SZ     4096
#define NPTS     (B_SZ * N_SZ)
#define ND       64
#define NCELL    (ND * ND)
#define WID      0.15f
#define X0       (-4.8f)
#define INVW     (1.0f / WID)
#define H2       (0.03f * 0.03f)
#define FULL     0xffffffffu

#define THREADS  256
#define NBLOCKS  256                          // 65536 threads, all co-resident

__device__ float4 g_aug[NPTS];
__device__ int    g_cell[NPTS];
__device__ int    g_rank[NPTS];
__device__ int    g_cnt[B_SZ * NCELL];        // zero-init; reset each run
__device__ float4 g_sorted[NPTS + 4];         // +pad (.bss zeros)
__device__ int    g_scell[NPTS];
__device__ int    g_sidx[NPTS];
__device__ int    g_cst[B_SZ * (NCELL + 1)];
__device__ float  g_loss[NPTS];
__device__ int    g_done;                     // zero-init; self-resetting
__device__ int    g_bar_count;                // zero-init; self-resetting
__device__ int    g_bar_gen;                  // monotone across replays

#define CE(x, y) { float t_ = fminf((x), (y)); (y) = fmaxf((x), (y)); (x) = t_; }

__device__ __forceinline__ void ins5(float& d0, float& d1, float& d2,
                                     float& d3, float& d4, float v) {
    d4 = fminf(d4, v);
    CE(d3, d4) CE(d2, d3) CE(d1, d2) CE(d0, d1)
}

__device__ __forceinline__ void grid_sync() {
    __syncthreads();
    if (threadIdx.x == 0) {
        int gen = *(volatile int*)&g_bar_gen;
        __threadfence();
        int t = atomicAdd(&g_bar_count, 1);
        if (t == NBLOCKS - 1) {
            g_bar_count = 0;
            __threadfence();
            atomicExch(&g_bar_gen, gen + 1);
        } else {
            while (*(volatile int*)&g_bar_gen == gen) { __nanosleep(20); }
        }
        __threadfence();
    }
    __syncthreads();
}

__global__ __launch_bounds__(THREADS)
void repulsion_fused_kernel(const float* __restrict__ pc,
                            float* __restrict__ out) {
    __shared__ int   swtot[THREADS / 32];     // 8 warp totals
    __shared__ float wsum[THREADS / 32];
    __shared__ int   is_last;

    const int tid  = threadIdx.x;
    const int gtid = blockIdx.x * THREADS + tid;      // 0..65535
    const int warp = tid >> 5;
    const int lane = tid & 31;

    // ---------------- phase A: prep (one point per thread) ----------------
    if (gtid < NPTS) {
        const int bt = gtid >> 12;
        const float* s = pc + (size_t)gtid * 3;
        float x = s[0], y = s[1], z = s[2];
        int bx = min(ND - 1, max(0, (int)((x - X0) * INVW)));
        int by = min(ND - 1, max(0, (int)((y - X0) * INVW)));
        int cell = bx * ND + by;
        g_aug[gtid]  = make_float4(x, y, z, fmaf(x, x, fmaf(y, y, z * z)));
        g_cell[gtid] = cell;
        g_rank[gtid] = atomicAdd(&g_cnt[bt * NCELL + cell], 1);
    }
    grid_sync();

    // ---------------- phase B: per-batch scan (blocks 0..7) ----------------
    if (blockIdx.x < B_SZ) {
        const int bt = blockIdx.x;
        int* cnt = g_cnt + bt * NCELL;
        int  c[16], pre[16];
        int  tsum = 0;
        #pragma unroll
        for (int j = 0; j < 16; ++j) {
            c[j] = cnt[tid * 16 + j];
            pre[j] = tsum;
            tsum += c[j];
        }
        int incl = tsum;
        #pragma unroll
        for (int o = 1; o < 32; o <<= 1) {
            int n = __shfl_up_sync(FULL, incl, o);
            if (lane >= o) incl += n;
        }
        if (lane == 31) swtot[warp] = incl;
        __syncthreads();
        if (warp == 0) {                       // ALL 32 lanes participate
            int v  = (lane < THREADS / 32) ? swtot[lane] : 0;
            int si = v;
            #pragma unroll
            for (int o = 1; o < 32; o <<= 1) {
                int n = __shfl_up_sync(FULL, si, o);
                if (lane >= o) si += n;
            }
            if (lane < THREADS / 32) swtot[lane] = si - v;
        }
        __syncthreads();
        int base = swtot[warp] + (incl - tsum);
        int* cst = g_cst + bt * (NCELL + 1);
        #pragma unroll
        for (int j = 0; j < 16; ++j) cst[tid * 16 + j] = base + pre[j];
        if (tid == 0) cst[NCELL] = N_SZ;
    }
    grid_sync();

    // ---------------- phase C: scatter + g_cnt reset ----------------
    if (gtid < NPTS) {
        const int bt = gtid >> 12;
        int cell = g_cell[gtid];
        int pos  = bt * N_SZ + g_cst[bt * (NCELL + 1) + cell] + g_rank[gtid];
        g_sorted[pos] = g_aug[gtid];
        g_scell[pos]  = cell;
        g_sidx[pos]   = gtid;
        g_cnt[gtid]   = 0;                    // NPTS == B_SZ*NCELL exactly
    }
    grid_sync();

    // ---------------- phase D: 3x3-window KNN (2 splits/query) -------------
    {
        const int s     = gtid >> 1;          // sorted query position
        const int split = gtid & 1;
        const int bt    = s >> 12;

        float4 q = g_sorted[s];
        const float m2x = -2.0f * q.x, m2y = -2.0f * q.y, m2z = -2.0f * q.z;
        const float qsq = q.w;

        const int  cell = g_scell[s];
        const int  bx = cell >> 6, by = cell & (ND - 1);
        const int* cst = g_cst + bt * (NCELL + 1);
        const int  rlo  = max(by - 1, 0);
        const int  rhi  = min(by + 2, ND);
        const int  cxlo = max(bx - 1, 0);
        const int  cxhi = min(bx + 1, ND - 1);
        const int  bbase = bt << 12;

        float d0 = FLT_MAX, d1 = FLT_MAX, d2 = FLT_MAX, d3 = FLT_MAX, d4 = FLT_MAX;

        for (int cx = cxlo; cx <= cxhi; ++cx) {
            const int clo = cst[cx * ND + rlo] + bbase;
            const int chi = cst[cx * ND + rhi] + bbase;
            const int cmid = (clo + chi) >> 1;
            const int lo = split ? cmid : clo;
            const int hi = split ? chi  : cmid;
            for (int i = lo; i < hi; i += 4) {
                float4 p0 = g_sorted[i];
                float4 p1 = g_sorted[i + 1];
                float4 p2 = g_sorted[i + 2];
                float4 p3 = g_sorted[i + 3];
                float va = fmaf(p0.x, m2x, fmaf(p0.y, m2y, fmaf(p0.z, m2z, p0.w)));
                float vb = fmaf(p1.x, m2x, fmaf(p1.y, m2y, fmaf(p1.z, m2z, p1.w)));
                float vc = fmaf(p2.x, m2x, fmaf(p2.y, m2y, fmaf(p2.z, m2z, p2.w)));
                float vd = fmaf(p3.x, m2x, fmaf(p3.y, m2y, fmaf(p3.z, m2z, p3.w)));
                vb = (i + 1 < hi) ? vb : FLT_MAX;   // tail guards
                vc = (i + 2 < hi) ? vc : FLT_MAX;
                vd = (i + 3 < hi) ? vd : FLT_MAX;
                CE(va, vb) CE(vc, vd) CE(va, vc) CE(vb, vd) CE(vb, vc)
                d1 = fminf(d1, vd); d2 = fminf(d2, vc);
                d3 = fminf(d3, vb); d4 = fminf(d4, va);
                CE(d0, d4) CE(d1, d3) CE(d2, d4) CE(d1, d2) CE(d3, d4)
            }
        }

        // Merge the two splits (lane pairs 2k, 2k+1) — full-warp collective.
        float o0 = __shfl_xor_sync(FULL, d0, 1);
        float o1 = __shfl_xor_sync(FULL, d1, 1);
        float o2 = __shfl_xor_sync(FULL, d2, 1);
        float o3 = __shfl_xor_sync(FULL, d3, 1);
        float o4 = __shfl_xor_sync(FULL, d4, 1);
        ins5(d0, d1, d2, d3, d4, o0);
        ins5(d0, d1, d2, d3, d4, o1);
        ins5(d0, d1, d2, d3, d4, o2);
        ins5(d0, d1, d2, d3, d4, o3);
        ins5(d0, d1, d2, d3, d4, o4);

        if (split == 0) {
            const float inv = -1.0f / H2;
            float loss = 0.0f, t;
            t = fmaxf(d1 + qsq, 0.0f); loss -= t * expf(t * inv);
            t = fmaxf(d2 + qsq, 0.0f); loss -= t * expf(t * inv);
            t = fmaxf(d3 + qsq, 0.0f); loss -= t * expf(t * inv);
            t = fmaxf(d4 + qsq, 0.0f); loss -= t * expf(t * inv);
            g_loss[g_sidx[s]] = loss;          // order-invariant value
        }
    }

    __threadfence();
    __syncthreads();
    if (tid == 0) {
        int n = atomicAdd(&g_done, 1);
        is_last = (n == NBLOCKS - 1);
    }
    __syncthreads();

    // Last block: deterministic fixed-order reduction over original indices.
    if (is_last) {
        __threadfence();
        const float4* lv = (const float4*)g_loss;
        float acc = 0.0f;
        #pragma unroll
        for (int j = 0; j < NPTS / 4 / THREADS; ++j) {    // 32 float4s/thread
            float4 v = lv[j * THREADS + tid];
            acc += (v.x + v.y) + (v.z + v.w);
        }
        #pragma unroll
        for (int o = 16; o > 0; o >>= 1)
            acc += __shfl_down_sync(FULL, acc, o);
        if (lane == 0) wsum[warp] = acc;
        __syncthreads();
        if (tid == 0) {
            float t = 0.0f;
            #pragma unroll
            for (int w = 0; w < THREADS / 32; ++w) t += wsum[w];
            out[0] = t;
            g_done = 0;                        // reset for next graph replay
        }
    }
}

extern "C" void kernel_launch(void* const* d_in, const int* in_sizes, int n_in,
                              void* d_out, int out_size) {
    const float* pc = (const float*)d_in[0];
    repulsion_fused_kernel<<<NBLOCKS, THREADS>>>(pc, (float*)d_out);
}

// round 15
// speedup vs baseline: 1.2867x; 1.2867x over previous
#include <cuda_runtime.h>
#include <math.h>
#include <float.h>

// RepulsionLoss: B=8, N=4096, KNN=4, H=0.03
// 2D grid pruning (64x64 cells, width 0.15): neighbors outside the 3x3 cell
// window have weight <= e^-25, negligible. Build: 3 wide kernels (prep ->
// scan -> scatter; unordered counting sort with atomic ranks — counts and
// cell starts are deterministic). Search: 3x3 window (~66 candidates),
// 2 splits/query, single top-5 list, 4-wide batches (empirically optimal).
// Selection = exact min/max network over the 5 smallest -> order-invariant;
// losses scattered to ORIGINAL indices, reduced in fixed order by the last
// block -> deterministic output. Self = strict min -> slot 0, dropped
// (matches reference top_k(KNN+1)-drop-first).

#define B_SZ     8
#define N_SZ     4096
#define NPTS     (B_SZ * N_SZ)
#define ND       64
#define NCELL    (ND * ND)
#define WID      0.15f
#define X0       (-4.8f)
#define INVW     (1.0f / WID)
#define H2       (0.03f * 0.03f)
#define FULL     0xffffffffu

#define STHREADS 256
#define SGRID    ((NPTS * 2) / STHREADS)     // 256 blocks, 2 splits/query

__device__ float4 g_aug[NPTS];               // (x,y,z,|p|^2) original order
__device__ int    g_cell[NPTS];
__device__ int    g_rank[NPTS];
__device__ int    g_cnt[B_SZ * NCELL];       // zero-init; self-resetting (K2)
__device__ float4 g_sorted[NPTS + 4];        // +pad (.bss zeros)
__device__ int    g_scell[NPTS];
__device__ int    g_sidx[NPTS];              // sorted pos -> original index
__device__ int    g_cst[B_SZ * (NCELL + 1)];
__device__ float  g_loss[NPTS];
__device__ int    g_done;                    // zero-init; self-resetting

#define CE(x, y) { float t_ = fminf((x), (y)); (y) = fmaxf((x), (y)); (x) = t_; }

__device__ __forceinline__ void ins5(float& d0, float& d1, float& d2,
                                     float& d3, float& d4, float v) {
    d4 = fminf(d4, v);
    CE(d3, d4) CE(d2, d3) CE(d1, d2) CE(d0, d1)
}

// K1: cells + atomic ranks + augmented points (32 blocks, full chip).
__global__ __launch_bounds__(1024)
void prep_kernel(const float* __restrict__ pc) {
    const int i  = blockIdx.x * 1024 + threadIdx.x;     // 0..NPTS-1
    const int bt = i >> 12;
    const float* s = pc + (size_t)i * 3;
    float x = s[0], y = s[1], z = s[2];
    int bx = min(ND - 1, max(0, (int)((x - X0) * INVW)));
    int by = min(ND - 1, max(0, (int)((y - X0) * INVW)));
    int cell = bx * ND + by;
    g_aug[i]  = make_float4(x, y, z, fmaf(x, x, fmaf(y, y, z * z)));
    g_cell[i] = cell;
    g_rank[i] = atomicAdd(&g_cnt[bt * NCELL + cell], 1);
}

// K2: per-batch exclusive scan of 4096 bins -> g_cst; resets g_cnt.
__global__ __launch_bounds__(1024)
void scan_kernel() {
    __shared__ int wtot[32];
    __shared__ int wpre[32];
    const int tid  = threadIdx.x;
    const int bt   = blockIdx.x;
    const int warp = tid >> 5;
    const int lane = tid & 31;

    int* cnt = g_cnt + bt * NCELL;
    int  c0 = cnt[tid * 4 + 0], c1 = cnt[tid * 4 + 1];
    int  c2 = cnt[tid * 4 + 2], c3 = cnt[tid * 4 + 3];
    cnt[tid * 4 + 0] = 0; cnt[tid * 4 + 1] = 0;          // reset for replay
    cnt[tid * 4 + 2] = 0; cnt[tid * 4 + 3] = 0;

    int tsum = c0 + c1 + c2 + c3;
    int incl = tsum;
    #pragma unroll
    for (int o = 1; o < 32; o <<= 1) {
        int n = __shfl_up_sync(FULL, incl, o);
        if (lane >= o) incl += n;
    }
    if (lane == 31) wtot[warp] = incl;
    __syncthreads();
    if (warp == 0) {
        int v = wtot[lane], si = v;
        #pragma unroll
        for (int o = 1; o < 32; o <<= 1) {
            int n = __shfl_up_sync(FULL, si, o);
            if (lane >= o) si += n;
        }
        wpre[lane] = si - v;
    }
    __syncthreads();

    int base = wpre[warp] + (incl - tsum);
    int* cst = g_cst + bt * (NCELL + 1);
    cst[tid * 4 + 0] = base;
    cst[tid * 4 + 1] = base + c0;
    cst[tid * 4 + 2] = base + c0 + c1;
    cst[tid * 4 + 3] = base + c0 + c1 + c2;
    if (tid == 0) cst[NCELL] = N_SZ;
}

// K3: scatter points into cell order.
__global__ __launch_bounds__(1024)
void scatter_kernel() {
    const int i  = blockIdx.x * 1024 + threadIdx.x;
    const int bt = i >> 12;
    int cell = g_cell[i];
    int pos  = bt * N_SZ + g_cst[bt * (NCELL + 1) + cell] + g_rank[i];
    g_sorted[pos] = g_aug[i];
    g_scell[pos]  = cell;
    g_sidx[pos]   = i;
}

// K4: 3x3-window KNN (2 splits/query) + loss + fused deterministic reduce.
__global__ __launch_bounds__(STHREADS)
void repulsion_grid_kernel(float* __restrict__ out) {
    __shared__ float wsum[STHREADS / 32];
    __shared__ int   is_last;

    const int g     = blockIdx.x * STHREADS + threadIdx.x;
    const int s     = g >> 1;                  // sorted query position
    const int split = g & 1;
    const int bt    = s >> 12;
    const int tid   = threadIdx.x;

    float4 q = g_sorted[s];
    const float m2x = -2.0f * q.x, m2y = -2.0f * q.y, m2z = -2.0f * q.z;
    const float qsq = q.w;

    const int  cell = g_scell[s];
    const int  bx = cell >> 6, by = cell & (ND - 1);
    const int* cst = g_cst + bt * (NCELL + 1);
    const int  rlo  = max(by - 1, 0);
    const int  rhi  = min(by + 2, ND);
    const int  cxlo = max(bx - 1, 0);
    const int  cxhi = min(bx + 1, ND - 1);
    const int  bbase = bt << 12;

    float d0 = FLT_MAX, d1 = FLT_MAX, d2 = FLT_MAX, d3 = FLT_MAX, d4 = FLT_MAX;

    for (int cx = cxlo; cx <= cxhi; ++cx) {
        const int clo = cst[cx * ND + rlo] + bbase;
        const int chi = cst[cx * ND + rhi] + bbase;
        const int cmid = (clo + chi) >> 1;
        const int lo = split ? cmid : clo;
        const int hi = split ? chi  : cmid;
        for (int i = lo; i < hi; i += 4) {
            float4 p0 = g_sorted[i];
            float4 p1 = g_sorted[i + 1];
            float4 p2 = g_sorted[i + 2];
            float4 p3 = g_sorted[i + 3];
            float va = fmaf(p0.x, m2x, fmaf(p0.y, m2y, fmaf(p0.z, m2z, p0.w)));
            float vb = fmaf(p1.x, m2x, fmaf(p1.y, m2y, fmaf(p1.z, m2z, p1.w)));
            float vc = fmaf(p2.x, m2x, fmaf(p2.y, m2y, fmaf(p2.z, m2z, p2.w)));
            float vd = fmaf(p3.x, m2x, fmaf(p3.y, m2y, fmaf(p3.z, m2z, p3.w)));
            vb = (i + 1 < hi) ? vb : FLT_MAX;   // tail guards
            vc = (i + 2 < hi) ? vc : FLT_MAX;
            vd = (i + 3 < hi) ? vd : FLT_MAX;
            CE(va, vb) CE(vc, vd) CE(va, vc) CE(vb, vd) CE(vb, vc)
            d1 = fminf(d1, vd); d2 = fminf(d2, vc);
            d3 = fminf(d3, vb); d4 = fminf(d4, va);
            CE(d0, d4) CE(d1, d3) CE(d2, d4) CE(d1, d2) CE(d3, d4)
        }
    }

    // Merge the two splits of this query (lane pairs 2k, 2k+1).
    {
        float o0 = __shfl_xor_sync(FULL, d0, 1);
        float o1 = __shfl_xor_sync(FULL, d1, 1);
        float o2 = __shfl_xor_sync(FULL, d2, 1);
        float o3 = __shfl_xor_sync(FULL, d3, 1);
        float o4 = __shfl_xor_sync(FULL, d4, 1);
        ins5(d0, d1, d2, d3, d4, o0);
        ins5(d0, d1, d2, d3, d4, o1);
        ins5(d0, d1, d2, d3, d4, o2);
        ins5(d0, d1, d2, d3, d4, o3);
        ins5(d0, d1, d2, d3, d4, o4);
    }

    if (split == 0) {
        const float inv = -1.0f / H2;
        float loss = 0.0f, t;
        t = fmaxf(d1 + qsq, 0.0f); loss -= t * expf(t * inv);
        t = fmaxf(d2 + qsq, 0.0f); loss -= t * expf(t * inv);
        t = fmaxf(d3 + qsq, 0.0f); loss -= t * expf(t * inv);
        t = fmaxf(d4 + qsq, 0.0f); loss -= t * expf(t * inv);
        g_loss[g_sidx[s]] = loss;              // order-invariant value
    }

    __threadfence();                           // publish g_loss writes
    __syncthreads();
    if (tid == 0) {
        int n = atomicAdd(&g_done, 1);
        is_last = (n == SGRID - 1);
    }
    __syncthreads();

    // Last block: deterministic fixed-order reduction over original indices.
    if (is_last) {
        __threadfence();
        const float4* lv = (const float4*)g_loss;
        float acc = 0.0f;
        #pragma unroll
        for (int j = 0; j < NPTS / 4 / STHREADS; ++j) {   // 32 float4s/thread
            float4 v = lv[j * STHREADS + tid];
            acc += (v.x + v.y) + (v.z + v.w);
        }
        #pragma unroll
        for (int o = 16; o > 0; o >>= 1)
            acc += __shfl_down_sync(FULL, acc, o);
        if ((tid & 31) == 0) wsum[tid >> 5] = acc;
        __syncthreads();
        if (tid == 0) {
            float t = 0.0f;
            #pragma unroll
            for (int w = 0; w < STHREADS / 32; ++w) t += wsum[w];
            out[0] = t;
            g_done = 0;                        // reset for next graph replay
        }
    }
}

extern "C" void kernel_launch(void* const* d_in, const int* in_sizes, int n_in,
                              void* d_out, int out_size) {
    const float* pc = (const float*)d_in[0];
    prep_kernel<<<NPTS / 1024, 1024>>>(pc);
    scan_kernel<<<B_SZ, 1024>>>();
    scatter_kernel<<<NPTS / 1024, 1024>>>();
    repulsion_grid_kernel<<<SGRID, STHREADS>>>((float*)d_out);
}